// round 6
// baseline (speedup 1.0000x reference)
#include <cuda_runtime.h>
#include <cuda_bf16.h>
#include <math.h>

// ----------------------------------------------------------------------------
// Problem constants: B=8, T=1024, D=1024, H=16, HD=64.  M = B*T = 8192.
// ----------------------------------------------------------------------------
#define M_ROWS 8192
#define DMODEL 1024
#define D3     3072
#define DFF    4096
#define NHEAD  16
#define HDIM   64
#define SEQ    1024

// ----------------------------------------------------------------------------
// Scratch buffers (device globals -- no cudaMalloc allowed)
// ----------------------------------------------------------------------------
__device__ float g_qkv[M_ROWS * D3];      // 96 MB
__device__ float g_ctx[M_ROWS * DMODEL];  // 32 MB
__device__ float g_tmp[M_ROWS * DMODEL];  // 32 MB (attn_out+res, later ff2+res)
__device__ float g_x1 [M_ROWS * DMODEL];  // 32 MB
__device__ float g_ffh[M_ROWS * DFF];     // 128 MB

// ----------------------------------------------------------------------------
// SGEMM: C[M,N] = A[M,K] @ B[K,N] + bias (+ epilogue)
// BM=BN=128, BK=8, 256 threads, 8x8 per-thread tile.
// EPI: 0 = bias only, 1 = bias + residual, 2 = bias + exact GELU
// All dims are multiples of the tile sizes (no bounds checks needed).
// ----------------------------------------------------------------------------
#define BM 128
#define BN 128
#define BK 8
#define TM 8
#define TN 8

__device__ __forceinline__ float gelu_exact(float x) {
    return 0.5f * x * (1.0f + erff(x * 0.70710678118654752440f));
}

template <int EPI>
__global__ __launch_bounds__(256) void gemm_kernel(
    const float* __restrict__ A, const float* __restrict__ B,
    const float* __restrict__ bias, const float* __restrict__ res,
    float* __restrict__ C, int M, int N, int K)
{
    __shared__ float As[BK][BM + 4];   // stride 132 floats (528B, 16B-aligned)
    __shared__ float Bs[BK][BN];

    const int tid = threadIdx.x;
    const int bm = blockIdx.y;
    const int bn = blockIdx.x;

    // A tile loading: 128 rows x 8 cols, one float4 per thread
    const int a_row  = tid >> 1;          // 0..127
    const int a_col4 = (tid & 1) * 4;     // 0 or 4
    // B tile loading: 8 rows x 128 cols, one float4 per thread
    const int b_row  = tid >> 5;          // 0..7
    const int b_col4 = (tid & 31) * 4;    // 0..124

    const float* Aptr = A + (size_t)(bm * BM + a_row) * K + a_col4;
    const float* Bptr = B + (size_t)b_row * N + bn * BN + b_col4;

    const int ty = tid >> 4;   // 0..15
    const int tx = tid & 15;   // 0..15

    float acc[TM][TN];
    #pragma unroll
    for (int i = 0; i < TM; i++)
        #pragma unroll
        for (int j = 0; j < TN; j++) acc[i][j] = 0.0f;

    for (int k0 = 0; k0 < K; k0 += BK) {
        float4 av = *(const float4*)Aptr;  Aptr += BK;
        float4 bv = *(const float4*)Bptr;  Bptr += (size_t)BK * N;

        As[a_col4 + 0][a_row] = av.x;
        As[a_col4 + 1][a_row] = av.y;
        As[a_col4 + 2][a_row] = av.z;
        As[a_col4 + 3][a_row] = av.w;
        *(float4*)&Bs[b_row][b_col4] = bv;
        __syncthreads();

        #pragma unroll
        for (int k = 0; k < BK; k++) {
            float a_frag[TM], b_frag[TN];
            float4 a0 = *(const float4*)&As[k][ty * TM];
            float4 a1 = *(const float4*)&As[k][ty * TM + 4];
            float4 b0 = *(const float4*)&Bs[k][tx * TN];
            float4 b1 = *(const float4*)&Bs[k][tx * TN + 4];
            a_frag[0]=a0.x; a_frag[1]=a0.y; a_frag[2]=a0.z; a_frag[3]=a0.w;
            a_frag[4]=a1.x; a_frag[5]=a1.y; a_frag[6]=a1.z; a_frag[7]=a1.w;
            b_frag[0]=b0.x; b_frag[1]=b0.y; b_frag[2]=b0.z; b_frag[3]=b0.w;
            b_frag[4]=b1.x; b_frag[5]=b1.y; b_frag[6]=b1.z; b_frag[7]=b1.w;
            #pragma unroll
            for (int i = 0; i < TM; i++)
                #pragma unroll
                for (int j = 0; j < TN; j++)
                    acc[i][j] += a_frag[i] * b_frag[j];
        }
        __syncthreads();
    }

    // Epilogue
    const int ncol = bn * BN + tx * TN;
    float4 bsv0 = *(const float4*)&bias[ncol];
    float4 bsv1 = *(const float4*)&bias[ncol + 4];
    float bvals[TN] = {bsv0.x, bsv0.y, bsv0.z, bsv0.w, bsv1.x, bsv1.y, bsv1.z, bsv1.w};

    #pragma unroll
    for (int i = 0; i < TM; i++) {
        const int m = bm * BM + ty * TM + i;
        float* crow = C + (size_t)m * N + ncol;
        float v[TN];
        #pragma unroll
        for (int j = 0; j < TN; j++) v[j] = acc[i][j] + bvals[j];
        if (EPI == 1) {
            const float* rrow = res + (size_t)m * N + ncol;
            float4 r0 = *(const float4*)rrow;
            float4 r1 = *(const float4*)(rrow + 4);
            v[0]+=r0.x; v[1]+=r0.y; v[2]+=r0.z; v[3]+=r0.w;
            v[4]+=r1.x; v[5]+=r1.y; v[6]+=r1.z; v[7]+=r1.w;
        }
        if (EPI == 2) {
            #pragma unroll
            for (int j = 0; j < TN; j++) v[j] = gelu_exact(v[j]);
        }
        float4 o0 = make_float4(v[0], v[1], v[2], v[3]);
        float4 o1 = make_float4(v[4], v[5], v[6], v[7]);
        *(float4*)crow       = o0;
        *(float4*)(crow + 4) = o1;
    }
}

// ----------------------------------------------------------------------------
// Flash-attention style kernel.
// Grid: (T/64 query tiles, B*H). Block: 64 threads; each thread owns one
// query row: s[64] scores and O[64] accumulator live in registers, so the
// online softmax needs no cross-thread reduction.
// Q staged transposed [d][q] (stride 65), K staged transposed [d][k]
// (stride 65, broadcast reads), V staged [k][d] (stride 64, float4-clean),
// sharing one smem buffer with K (loaded after S is computed).
// ----------------------------------------------------------------------------
#define QTILE 64

__global__ __launch_bounds__(64) void attn_kernel(
    const float* __restrict__ qkv, float* __restrict__ ctx)
{
    __shared__ float Qs[QTILE * 65];   // [d][q], index d*65+q
    __shared__ float KV[QTILE * 65];   // K phase: [d][k] d*65+k ; V phase: [k][d] k*64+d

    const int tid = threadIdx.x;          // 0..63
    const int bh  = blockIdx.y;           // 0..127
    const int b   = bh >> 4;
    const int h   = bh & 15;
    const int q0  = blockIdx.x * QTILE;
    const float scale = 0.125f;           // 1/sqrt(64)

    const int lr = tid >> 4;              // 0..3 (row within 4-row load group)
    const int ld = (tid & 15) * 4;        // 0,4,...,60 (float4 col)

    // ---- load Q tile transposed into Qs[d][q] ----
    {
        const float* base = qkv + (size_t)(b * SEQ + q0) * D3 + h * HDIM;
        #pragma unroll
        for (int r0 = 0; r0 < QTILE; r0 += 4) {
            int q = r0 + lr;
            float4 v = *(const float4*)(base + (size_t)q * D3 + ld);
            Qs[(ld + 0) * 65 + q] = v.x;
            Qs[(ld + 1) * 65 + q] = v.y;
            Qs[(ld + 2) * 65 + q] = v.z;
            Qs[(ld + 3) * 65 + q] = v.w;
        }
    }

    float O[HDIM];
    #pragma unroll
    for (int d = 0; d < HDIM; d++) O[d] = 0.0f;
    float m_i = -1e30f;
    float l_i = 0.0f;

    for (int kt = 0; kt < SEQ / QTILE; kt++) {
        const float* kbase = qkv + (size_t)(b * SEQ + kt * QTILE) * D3 + DMODEL + h * HDIM;
        const float* vbase = kbase + DMODEL;

        __syncthreads();   // protect KV (prior V reads) before K overwrite
        // ---- load K tile transposed into KV[d][k] ----
        #pragma unroll
        for (int r0 = 0; r0 < QTILE; r0 += 4) {
            int k = r0 + lr;
            float4 v = *(const float4*)(kbase + (size_t)k * D3 + ld);
            KV[(ld + 0) * 65 + k] = v.x;
            KV[(ld + 1) * 65 + k] = v.y;
            KV[(ld + 2) * 65 + k] = v.z;
            KV[(ld + 3) * 65 + k] = v.w;
        }
        __syncthreads();

        // ---- S = Q K^T for this thread's query row ----
        float s[QTILE];
        #pragma unroll
        for (int k = 0; k < QTILE; k++) s[k] = 0.0f;
        #pragma unroll 4
        for (int d = 0; d < HDIM; d++) {
            float qd = Qs[d * 65 + tid];
            #pragma unroll
            for (int k4 = 0; k4 < QTILE; k4 += 4) {
                float4 kv = *(const float4*)&KV[d * 65 + k4];
                s[k4 + 0] += qd * kv.x;
                s[k4 + 1] += qd * kv.y;
                s[k4 + 2] += qd * kv.z;
                s[k4 + 3] += qd * kv.w;
            }
        }

        __syncthreads();   // done reading K; reuse buffer for V
        // ---- load V tile into KV[k][d] (stride 64, float4 stores) ----
        #pragma unroll
        for (int r0 = 0; r0 < QTILE; r0 += 4) {
            int k = r0 + lr;
            float4 v = *(const float4*)(vbase + (size_t)k * D3 + ld);
            *(float4*)&KV[k * 64 + ld] = v;
        }

        // ---- online softmax (thread-local: full row in registers) ----
        float tmax = -1e30f;
        #pragma unroll
        for (int k = 0; k < QTILE; k++) { s[k] *= scale; tmax = fmaxf(tmax, s[k]); }
        float m_new = fmaxf(m_i, tmax);
        float corr  = __expf(m_i - m_new);
        float ssum  = 0.0f;
        #pragma unroll
        for (int k = 0; k < QTILE; k++) { s[k] = __expf(s[k] - m_new); ssum += s[k]; }
        l_i = l_i * corr + ssum;
        m_i = m_new;
        #pragma unroll
        for (int d = 0; d < HDIM; d++) O[d] *= corr;

        __syncthreads();   // V tile visible

        // ---- O += P @ V ----
        #pragma unroll 4
        for (int k = 0; k < QTILE; k++) {
            float pk = s[k];
            #pragma unroll
            for (int d4 = 0; d4 < HDIM; d4 += 4) {
                float4 vv = *(const float4*)&KV[k * 64 + d4];
                O[d4 + 0] += pk * vv.x;
                O[d4 + 1] += pk * vv.y;
                O[d4 + 2] += pk * vv.z;
                O[d4 + 3] += pk * vv.w;
            }
        }
    }

    // ---- write ctx[b, t, h*64 + d] = O/l ----
    {
        float inv = 1.0f / l_i;
        float* out = ctx + (size_t)(b * SEQ + q0 + tid) * DMODEL + h * HDIM;
        #pragma unroll
        for (int d4 = 0; d4 < HDIM; d4 += 4) {
            float4 o = make_float4(O[d4]*inv, O[d4+1]*inv, O[d4+2]*inv, O[d4+3]*inv);
            *(float4*)(out + d4) = o;
        }
    }
}

// ----------------------------------------------------------------------------
// LayerNorm: one block per row of 1024, 256 threads (4 elems / thread).
// Population variance, eps = 1e-5 (matches jnp.var + rsqrt).
// ----------------------------------------------------------------------------
__global__ __launch_bounds__(256) void ln_kernel(
    const float* __restrict__ x, const float* __restrict__ g,
    const float* __restrict__ beta, float* __restrict__ y)
{
    const int row = blockIdx.x;
    const int tid = threadIdx.x;
    const float* xr = x + (size_t)row * DMODEL;

    float4 v = *(const float4*)(xr + tid * 4);
    float s  = v.x + v.y + v.z + v.w;
    float sq = v.x*v.x + v.y*v.y + v.z*v.z + v.w*v.w;

    #pragma unroll
    for (int off = 16; off > 0; off >>= 1) {
        s  += __shfl_xor_sync(0xffffffffu, s,  off);
        sq += __shfl_xor_sync(0xffffffffu, sq, off);
    }
    __shared__ float ss[8], ssq[8];
    if ((tid & 31) == 0) { ss[tid >> 5] = s; ssq[tid >> 5] = sq; }
    __syncthreads();
    float tot = 0.0f, totq = 0.0f;
    #pragma unroll
    for (int i = 0; i < 8; i++) { tot += ss[i]; totq += ssq[i]; }

    const float mu   = tot * (1.0f / DMODEL);
    const float var  = totq * (1.0f / DMODEL) - mu * mu;
    const float rstd = rsqrtf(var + 1e-5f);

    float4 gg = *(const float4*)(g + tid * 4);
    float4 bb = *(const float4*)(beta + tid * 4);
    float4 o;
    o.x = (v.x - mu) * rstd * gg.x + bb.x;
    o.y = (v.y - mu) * rstd * gg.y + bb.y;
    o.z = (v.z - mu) * rstd * gg.z + bb.z;
    o.w = (v.w - mu) * rstd * gg.w + bb.w;
    *(float4*)(y + (size_t)row * DMODEL + tid * 4) = o;
}

// ----------------------------------------------------------------------------
// kernel_launch
// Inputs (metadata order):
//  0 X, 1 W_qkv, 2 b_qkv, 3 W_out, 4 b_out, 5 ln1_g, 6 ln1_b,
//  7 ln2_g, 8 ln2_b, 9 W_ff1, 10 b_ff1, 11 W_ff2, 12 b_ff2
// ----------------------------------------------------------------------------
extern "C" void kernel_launch(void* const* d_in, const int* in_sizes, int n_in,
                              void* d_out, int out_size)
{
    const float* X      = (const float*)d_in[0];
    const float* W_qkv  = (const float*)d_in[1];
    const float* b_qkv  = (const float*)d_in[2];
    const float* W_out  = (const float*)d_in[3];
    const float* b_out  = (const float*)d_in[4];
    const float* ln1_g  = (const float*)d_in[5];
    const float* ln1_b  = (const float*)d_in[6];
    const float* ln2_g  = (const float*)d_in[7];
    const float* ln2_b  = (const float*)d_in[8];
    const float* W_ff1  = (const float*)d_in[9];
    const float* b_ff1  = (const float*)d_in[10];
    const float* W_ff2  = (const float*)d_in[11];
    const float* b_ff2  = (const float*)d_in[12];
    float* out = (float*)d_out;

    float *qkv, *ctx, *tmp, *x1, *ffh;
    cudaGetSymbolAddress((void**)&qkv, g_qkv);
    cudaGetSymbolAddress((void**)&ctx, g_ctx);
    cudaGetSymbolAddress((void**)&tmp, g_tmp);
    cudaGetSymbolAddress((void**)&x1,  g_x1);
    cudaGetSymbolAddress((void**)&ffh, g_ffh);

    // 1) QKV projection: [8192,1024] @ [1024,3072] + b
    gemm_kernel<0><<<dim3(D3 / BN, M_ROWS / BM), 256>>>(
        X, W_qkv, b_qkv, nullptr, qkv, M_ROWS, D3, DMODEL);

    // 2) Attention
    attn_kernel<<<dim3(SEQ / QTILE, 8 * NHEAD), 64>>>(qkv, ctx);

    // 3) Output projection + residual(X)
    gemm_kernel<1><<<dim3(DMODEL / BN, M_ROWS / BM), 256>>>(
        ctx, W_out, b_out, X, tmp, M_ROWS, DMODEL, DMODEL);

    // 4) LayerNorm 1 -> X1
    ln_kernel<<<M_ROWS, 256>>>(tmp, ln1_g, ln1_b, x1);

    // 5) FF1 + GELU: [8192,1024] @ [1024,4096]
    gemm_kernel<2><<<dim3(DFF / BN, M_ROWS / BM), 256>>>(
        x1, W_ff1, b_ff1, nullptr, ffh, M_ROWS, DFF, DMODEL);

    // 6) FF2 + residual(X1): [8192,4096] @ [4096,1024]
    gemm_kernel<1><<<dim3(DMODEL / BN, M_ROWS / BM), 256>>>(
        ffh, W_ff2, b_ff2, x1, tmp, M_ROWS, DMODEL, DFF);

    // 7) LayerNorm 2 -> out
    ln_kernel<<<M_ROWS, 256>>>(tmp, ln2_g, ln2_b, out);
}

// round 8
// speedup vs baseline: 1.7556x; 1.7556x over previous
#include <cuda_runtime.h>
#include <cuda_bf16.h>
#include <math.h>
#include <stdint.h>

// ----------------------------------------------------------------------------
// Problem constants: B=8, T=1024, D=1024, H=16, HD=64.  M = B*T = 8192.
// ----------------------------------------------------------------------------
#define M_ROWS 8192
#define DMODEL 1024
#define D3     3072
#define DFF    4096
#define NHEAD  16
#define HDIM   64
#define SEQ    1024

// ----------------------------------------------------------------------------
// Scratch (device globals -- no cudaMalloc allowed)
// ----------------------------------------------------------------------------
__device__ float g_qkv[M_ROWS * D3];        // 96 MB (fp32, attention input)
__device__ float g_ctx[M_ROWS * DMODEL];    // 32 MB
__device__ float g_tmp[M_ROWS * DMODEL];    // 32 MB
__device__ float g_x1 [M_ROWS * DMODEL];    // 32 MB
__device__ __nv_bfloat16 g_act_h[M_ROWS * DMODEL];   // activation hi
__device__ __nv_bfloat16 g_act_l[M_ROWS * DMODEL];   // activation lo
__device__ __nv_bfloat16 g_ffh_h[M_ROWS * DFF];      // FF1 out hi
__device__ __nv_bfloat16 g_ffh_l[M_ROWS * DFF];      // FF1 out lo
// weights, transposed to [N,K], split hi/lo
__device__ __nv_bfloat16 g_wqkv_h[DMODEL * D3];
__device__ __nv_bfloat16 g_wqkv_l[DMODEL * D3];
__device__ __nv_bfloat16 g_wout_h[DMODEL * DMODEL];
__device__ __nv_bfloat16 g_wout_l[DMODEL * DMODEL];
__device__ __nv_bfloat16 g_wff1_h[DMODEL * DFF];
__device__ __nv_bfloat16 g_wff1_l[DMODEL * DFF];
__device__ __nv_bfloat16 g_wff2_h[DFF * DMODEL];
__device__ __nv_bfloat16 g_wff2_l[DFF * DMODEL];

// ----------------------------------------------------------------------------
// PTX helpers (compute_103-baseline legal: cp.async / ldmatrix / mma.sync)
// ----------------------------------------------------------------------------
__device__ __forceinline__ uint32_t smem_to_u32(const void* smem_ptr) {
    uint32_t addr;
    asm("{ .reg .u64 tmp; cvta.to.shared.u64 tmp, %1; cvt.u32.u64 %0, tmp; }"
        : "=r"(addr) : "l"(smem_ptr));
    return addr;
}

__device__ __forceinline__ void cp16(uint32_t smem_addr, const void* gptr) {
    asm volatile("cp.async.cg.shared.global [%0], [%1], 16;"
                 :: "r"(smem_addr), "l"(gptr));
}
#define CP_COMMIT() asm volatile("cp.async.commit_group;" ::: "memory")
#define CP_WAIT1()  asm volatile("cp.async.wait_group 1;" ::: "memory")

__device__ __forceinline__ void ldsm4(uint32_t* d, uint32_t addr) {
    asm volatile("ldmatrix.sync.aligned.m8n8.x4.shared.b16 {%0,%1,%2,%3}, [%4];"
        : "=r"(d[0]), "=r"(d[1]), "=r"(d[2]), "=r"(d[3]) : "r"(addr));
}
__device__ __forceinline__ void ldsm2(uint32_t* d, uint32_t addr) {
    asm volatile("ldmatrix.sync.aligned.m8n8.x2.shared.b16 {%0,%1}, [%2];"
        : "=r"(d[0]), "=r"(d[1]) : "r"(addr));
}

__device__ __forceinline__ void mma16816(float* c, const uint32_t* a, const uint32_t* b) {
    asm volatile("mma.sync.aligned.m16n8k16.row.col.f32.bf16.bf16.f32 "
        "{%0,%1,%2,%3}, {%4,%5,%6,%7}, {%8,%9}, {%0,%1,%2,%3};"
        : "+f"(c[0]), "+f"(c[1]), "+f"(c[2]), "+f"(c[3])
        : "r"(a[0]), "r"(a[1]), "r"(a[2]), "r"(a[3]), "r"(b[0]), "r"(b[1]));
}

// ----------------------------------------------------------------------------
// Split conversions: fp32 -> (bf16 hi, bf16 lo) so  x ~= hi + lo
// ----------------------------------------------------------------------------
__device__ __forceinline__ void split2(float a, float b, uint32_t& h, uint32_t& l) {
    __nv_bfloat16 ha = __float2bfloat16(a);
    __nv_bfloat16 hb = __float2bfloat16(b);
    __nv_bfloat16 la = __float2bfloat16(a - __bfloat162float(ha));
    __nv_bfloat16 lb = __float2bfloat16(b - __bfloat162float(hb));
    __nv_bfloat162 hp(ha, hb), lp(la, lb);
    h = *(uint32_t*)&hp; l = *(uint32_t*)&lp;
}

__global__ __launch_bounds__(256) void convert_split_kernel(
    const float* __restrict__ x, __nv_bfloat16* __restrict__ h,
    __nv_bfloat16* __restrict__ l, int n4)
{
    int i = blockIdx.x * 256 + threadIdx.x;
    if (i >= n4) return;
    float4 v = ((const float4*)x)[i];
    uint32_t h0, l0, h1, l1;
    split2(v.x, v.y, h0, l0);
    split2(v.z, v.w, h1, l1);
    ((uint2*)h)[i] = make_uint2(h0, h1);
    ((uint2*)l)[i] = make_uint2(l0, l1);
}

// W [K,N] fp32 row-major -> Wt hi/lo [N,K] bf16 (32x32 tiles)
__global__ __launch_bounds__(256) void transpose_split_kernel(
    const float* __restrict__ W, __nv_bfloat16* __restrict__ h,
    __nv_bfloat16* __restrict__ l, int K, int N)
{
    __shared__ float t[32][33];
    const int tx = threadIdx.x;          // 0..31
    const int ty = threadIdx.y;          // 0..7
    const int k0 = blockIdx.y * 32;
    const int n0 = blockIdx.x * 32;
    #pragma unroll
    for (int r = 0; r < 4; r++)
        t[ty * 4 + r][tx] = W[(size_t)(k0 + ty * 4 + r) * N + n0 + tx];
    __syncthreads();
    #pragma unroll
    for (int r = 0; r < 4; r++) {
        int n = n0 + ty * 4 + r;
        float v = t[tx][ty * 4 + r];
        __nv_bfloat16 hv = __float2bfloat16(v);
        __nv_bfloat16 lv = __float2bfloat16(v - __bfloat162float(hv));
        h[(size_t)n * K + k0 + tx] = hv;
        l[(size_t)n * K + k0 + tx] = lv;
    }
}

// ----------------------------------------------------------------------------
// mma.sync split-bf16 GEMM:  C[M,N] = A[M,K] @ Bt[N,K]^T + bias (+ epilogue)
//   A ~ Ah + Al (bf16 [M,K]);  B ~ Bh + Bl (bf16 [N,K]).
//   A*B ~= Ah*Bh + Ah*Bl + Al*Bh  (fp32 accumulation).
// Tile: 128x128, BK=32, 256 threads (8 warps, each 64x32), 3-stage cp.async.
// Smem rows padded to 40 halves (80 B) -> conflict-free ldmatrix.
// EPI: 0 = bias -> fp32;  1 = bias + residual -> fp32;
//      2 = bias + exact GELU -> split bf16 (Ch, Cl)
// ----------------------------------------------------------------------------
#define BM 128
#define BN 128
#define BK 32
#define ROWB 80            // bytes per smem row (40 halves)
#define AH_OFF 0
#define AL_OFF 10240
#define BH_OFF 20480
#define BL_OFF 30720
#define STAGE_BYTES 40960
#define GEMM_SMEM (3 * STAGE_BYTES)   // 122880

__device__ __forceinline__ float gelu_exact(float x) {
    return 0.5f * x * (1.0f + erff(x * 0.70710678118654752440f));
}

template <int EPI>
__global__ __launch_bounds__(256) void gemm_mma(
    const __nv_bfloat16* __restrict__ Ah, const __nv_bfloat16* __restrict__ Al,
    const __nv_bfloat16* __restrict__ Bh, const __nv_bfloat16* __restrict__ Bl,
    const float* __restrict__ bias, const float* __restrict__ res,
    float* __restrict__ C, __nv_bfloat16* __restrict__ Ch,
    __nv_bfloat16* __restrict__ Cl, int N, int K)
{
    extern __shared__ char smem[];
    const uint32_t sbase = smem_to_u32(smem);
    const int tid  = threadIdx.x;
    const int wid  = tid >> 5;
    const int lane = tid & 31;
    const int m0 = blockIdx.y * BM;
    const int n0 = blockIdx.x * BN;

    // loader mapping: thread -> one row, two 16B chunks
    const int r  = tid >> 1;            // 0..127
    const int c2 = (tid & 1) * 2;       // chunk 0/2

    // warp tile
    const int wm = (wid & 1) * 64;
    const int wn = (wid >> 1) * 32;

    float acc[4][4][4];
    #pragma unroll
    for (int i = 0; i < 4; i++)
        #pragma unroll
        for (int j = 0; j < 4; j++)
            #pragma unroll
            for (int k = 0; k < 4; k++) acc[i][j][k] = 0.0f;

    const int KT = K / BK;

    auto load_stage = [&](int it, int s) {
        const int kc = it * BK;
        const uint32_t st = sbase + s * STAGE_BYTES;
        const uint32_t sa = st + r * ROWB + c2 * 16;
        const size_t ga = (size_t)(m0 + r) * K + kc + c2 * 8;
        const size_t gb = (size_t)(n0 + r) * K + kc + c2 * 8;
        cp16(sa + AH_OFF,      Ah + ga);
        cp16(sa + AH_OFF + 16, Ah + ga + 8);
        cp16(sa + AL_OFF,      Al + ga);
        cp16(sa + AL_OFF + 16, Al + ga + 8);
        cp16(sa + BH_OFF,      Bh + gb);
        cp16(sa + BH_OFF + 16, Bh + gb + 8);
        cp16(sa + BL_OFF,      Bl + gb);
        cp16(sa + BL_OFF + 16, Bl + gb + 8);
    };

    // prologue: stages 0,1
    load_stage(0, 0); CP_COMMIT();
    load_stage(1, 1); CP_COMMIT();

    for (int it = 0; it < KT; it++) {
        CP_WAIT1();
        __syncthreads();
        const int nx = it + 2;
        if (nx < KT) load_stage(nx, nx % 3);
        CP_COMMIT();   // always commit (possibly empty) to keep wait semantics exact

        const uint32_t st = sbase + (it % 3) * STAGE_BYTES;
        #pragma unroll
        for (int ks = 0; ks < 2; ks++) {
            const int kb = (ks * 16 + (lane >> 4) * 8) * 2;        // A k-offset bytes
            const int kbB = (ks * 16 + ((lane >> 3) & 1) * 8) * 2; // B k-offset bytes
            uint32_t a_h[4][4], a_l[4][4], b_h[4][2], b_l[4][2];
            #pragma unroll
            for (int mf = 0; mf < 4; mf++) {
                uint32_t ra = st + (wm + mf * 16 + (lane & 15)) * ROWB + kb;
                ldsm4(a_h[mf], ra + AH_OFF);
                ldsm4(a_l[mf], ra + AL_OFF);
            }
            #pragma unroll
            for (int nf = 0; nf < 4; nf++) {
                uint32_t rb = st + (wn + nf * 8 + (lane & 7)) * ROWB + kbB;
                ldsm2(b_h[nf], rb + BH_OFF);
                ldsm2(b_l[nf], rb + BL_OFF);
            }
            #pragma unroll
            for (int mf = 0; mf < 4; mf++)
                #pragma unroll
                for (int nf = 0; nf < 4; nf++) {
                    mma16816(acc[mf][nf], a_h[mf], b_h[nf]);
                    mma16816(acc[mf][nf], a_h[mf], b_l[nf]);
                    mma16816(acc[mf][nf], a_l[mf], b_h[nf]);
                }
        }
    }

    // ---- epilogue (register-resident) ----
    #pragma unroll
    for (int mf = 0; mf < 4; mf++) {
        const int m = m0 + wm + mf * 16 + (lane >> 2);
        #pragma unroll
        for (int nf = 0; nf < 4; nf++) {
            const int n = n0 + wn + nf * 8 + (lane & 3) * 2;
            float2 bv = *(const float2*)(bias + n);
            float* a = acc[mf][nf];
            float v0 = a[0] + bv.x, v1 = a[1] + bv.y;   // row m
            float v2 = a[2] + bv.x, v3 = a[3] + bv.y;   // row m+8
            if (EPI == 1) {
                float2 r0 = *(const float2*)(res + (size_t)m * N + n);
                float2 r1 = *(const float2*)(res + (size_t)(m + 8) * N + n);
                v0 += r0.x; v1 += r0.y; v2 += r1.x; v3 += r1.y;
            }
            if (EPI == 2) {
                v0 = gelu_exact(v0); v1 = gelu_exact(v1);
                v2 = gelu_exact(v2); v3 = gelu_exact(v3);
                uint32_t h0, l0, h1, l1;
                split2(v0, v1, h0, l0);
                split2(v2, v3, h1, l1);
                *(uint32_t*)(Ch + (size_t)m * N + n)       = h0;
                *(uint32_t*)(Cl + (size_t)m * N + n)       = l0;
                *(uint32_t*)(Ch + (size_t)(m + 8) * N + n) = h1;
                *(uint32_t*)(Cl + (size_t)(m + 8) * N + n) = l1;
            } else {
                *(float2*)(C + (size_t)m * N + n)       = make_float2(v0, v1);
                *(float2*)(C + (size_t)(m + 8) * N + n) = make_float2(v2, v3);
            }
        }
    }
}

// ----------------------------------------------------------------------------
// Flash-attention style kernel (fp32 SIMT; unchanged from passing R5/R6 base).
// ----------------------------------------------------------------------------
#define QTILE 64

__global__ __launch_bounds__(64) void attn_kernel(
    const float* __restrict__ qkv, float* __restrict__ ctx)
{
    __shared__ float Qs[QTILE * 65];
    __shared__ float KV[QTILE * 65];

    const int tid = threadIdx.x;
    const int bh  = blockIdx.y;
    const int b   = bh >> 4;
    const int h   = bh & 15;
    const int q0  = blockIdx.x * QTILE;
    const float scale = 0.125f;

    const int lr = tid >> 4;
    const int ld = (tid & 15) * 4;

    {
        const float* base = qkv + (size_t)(b * SEQ + q0) * D3 + h * HDIM;
        #pragma unroll
        for (int r0 = 0; r0 < QTILE; r0 += 4) {
            int q = r0 + lr;
            float4 v = *(const float4*)(base + (size_t)q * D3 + ld);
            Qs[(ld + 0) * 65 + q] = v.x;
            Qs[(ld + 1) * 65 + q] = v.y;
            Qs[(ld + 2) * 65 + q] = v.z;
            Qs[(ld + 3) * 65 + q] = v.w;
        }
    }

    float O[HDIM];
    #pragma unroll
    for (int d = 0; d < HDIM; d++) O[d] = 0.0f;
    float m_i = -1e30f;
    float l_i = 0.0f;

    for (int kt = 0; kt < SEQ / QTILE; kt++) {
        const float* kbase = qkv + (size_t)(b * SEQ + kt * QTILE) * D3 + DMODEL + h * HDIM;
        const float* vbase = kbase + DMODEL;

        __syncthreads();
        #pragma unroll
        for (int r0 = 0; r0 < QTILE; r0 += 4) {
            int k = r0 + lr;
            float4 v = *(const float4*)(kbase + (size_t)k * D3 + ld);
            KV[(ld + 0) * 65 + k] = v.x;
            KV[(ld + 1) * 65 + k] = v.y;
            KV[(ld + 2) * 65 + k] = v.z;
            KV[(ld + 3) * 65 + k] = v.w;
        }
        __syncthreads();

        float s[QTILE];
        #pragma unroll
        for (int k = 0; k < QTILE; k++) s[k] = 0.0f;
        #pragma unroll 4
        for (int d = 0; d < HDIM; d++) {
            float qd = Qs[d * 65 + tid];
            #pragma unroll
            for (int k4 = 0; k4 < QTILE; k4 += 4) {
                float4 kv = *(const float4*)&KV[d * 65 + k4];
                s[k4 + 0] += qd * kv.x;
                s[k4 + 1] += qd * kv.y;
                s[k4 + 2] += qd * kv.z;
                s[k4 + 3] += qd * kv.w;
            }
        }

        __syncthreads();
        #pragma unroll
        for (int r0 = 0; r0 < QTILE; r0 += 4) {
            int k = r0 + lr;
            float4 v = *(const float4*)(vbase + (size_t)k * D3 + ld);
            *(float4*)&KV[k * 64 + ld] = v;
        }

        float tmax = -1e30f;
        #pragma unroll
        for (int k = 0; k < QTILE; k++) { s[k] *= scale; tmax = fmaxf(tmax, s[k]); }
        float m_new = fmaxf(m_i, tmax);
        float corr  = __expf(m_i - m_new);
        float ssum  = 0.0f;
        #pragma unroll
        for (int k = 0; k < QTILE; k++) { s[k] = __expf(s[k] - m_new); ssum += s[k]; }
        l_i = l_i * corr + ssum;
        m_i = m_new;
        #pragma unroll
        for (int d = 0; d < HDIM; d++) O[d] *= corr;

        __syncthreads();

        #pragma unroll 4
        for (int k = 0; k < QTILE; k++) {
            float pk = s[k];
            #pragma unroll
            for (int d4 = 0; d4 < HDIM; d4 += 4) {
                float4 vv = *(const float4*)&KV[k * 64 + d4];
                O[d4 + 0] += pk * vv.x;
                O[d4 + 1] += pk * vv.y;
                O[d4 + 2] += pk * vv.z;
                O[d4 + 3] += pk * vv.w;
            }
        }
    }

    {
        float inv = 1.0f / l_i;
        float* out = ctx + (size_t)(b * SEQ + q0 + tid) * DMODEL + h * HDIM;
        #pragma unroll
        for (int d4 = 0; d4 < HDIM; d4 += 4) {
            float4 o = make_float4(O[d4]*inv, O[d4+1]*inv, O[d4+2]*inv, O[d4+3]*inv);
            *(float4*)(out + d4) = o;
        }
    }
}

// ----------------------------------------------------------------------------
// LayerNorm; SPLIT=1 additionally emits bf16 hi/lo of the output
// ----------------------------------------------------------------------------
template <int SPLIT>
__global__ __launch_bounds__(256) void ln_kernel(
    const float* __restrict__ x, const float* __restrict__ g,
    const float* __restrict__ beta, float* __restrict__ y,
    __nv_bfloat16* __restrict__ yh, __nv_bfloat16* __restrict__ yl)
{
    const int row = blockIdx.x;
    const int tid = threadIdx.x;
    const float* xr = x + (size_t)row * DMODEL;

    float4 v = *(const float4*)(xr + tid * 4);
    float s  = v.x + v.y + v.z + v.w;
    float sq = v.x*v.x + v.y*v.y + v.z*v.z + v.w*v.w;

    #pragma unroll
    for (int off = 16; off > 0; off >>= 1) {
        s  += __shfl_xor_sync(0xffffffffu, s,  off);
        sq += __shfl_xor_sync(0xffffffffu, sq, off);
    }
    __shared__ float ss[8], ssq[8];
    if ((tid & 31) == 0) { ss[tid >> 5] = s; ssq[tid >> 5] = sq; }
    __syncthreads();
    float tot = 0.0f, totq = 0.0f;
    #pragma unroll
    for (int i = 0; i < 8; i++) { tot += ss[i]; totq += ssq[i]; }

    const float mu   = tot * (1.0f / DMODEL);
    const float var  = totq * (1.0f / DMODEL) - mu * mu;
    const float rstd = rsqrtf(var + 1e-5f);

    float4 gg = *(const float4*)(g + tid * 4);
    float4 bb = *(const float4*)(beta + tid * 4);
    float4 o;
    o.x = (v.x - mu) * rstd * gg.x + bb.x;
    o.y = (v.y - mu) * rstd * gg.y + bb.y;
    o.z = (v.z - mu) * rstd * gg.z + bb.z;
    o.w = (v.w - mu) * rstd * gg.w + bb.w;
    *(float4*)(y + (size_t)row * DMODEL + tid * 4) = o;

    if (SPLIT) {
        uint32_t h0, l0, h1, l1;
        split2(o.x, o.y, h0, l0);
        split2(o.z, o.w, h1, l1);
        ((uint2*)(yh + (size_t)row * DMODEL))[tid] = make_uint2(h0, h1);
        ((uint2*)(yl + (size_t)row * DMODEL))[tid] = make_uint2(l0, l1);
    }
}

// ----------------------------------------------------------------------------
// kernel_launch
// Inputs: 0 X, 1 W_qkv, 2 b_qkv, 3 W_out, 4 b_out, 5 ln1_g, 6 ln1_b,
//         7 ln2_g, 8 ln2_b, 9 W_ff1, 10 b_ff1, 11 W_ff2, 12 b_ff2
// ----------------------------------------------------------------------------
extern "C" void kernel_launch(void* const* d_in, const int* in_sizes, int n_in,
                              void* d_out, int out_size)
{
    const float* X      = (const float*)d_in[0];
    const float* W_qkv  = (const float*)d_in[1];
    const float* b_qkv  = (const float*)d_in[2];
    const float* W_out  = (const float*)d_in[3];
    const float* b_out  = (const float*)d_in[4];
    const float* ln1_g  = (const float*)d_in[5];
    const float* ln1_b  = (const float*)d_in[6];
    const float* ln2_g  = (const float*)d_in[7];
    const float* ln2_b  = (const float*)d_in[8];
    const float* W_ff1  = (const float*)d_in[9];
    const float* b_ff1  = (const float*)d_in[10];
    const float* W_ff2  = (const float*)d_in[11];
    const float* b_ff2  = (const float*)d_in[12];
    float* out = (float*)d_out;

    float *qkv, *ctx, *tmp, *x1;
    __nv_bfloat16 *ah, *al, *fh, *fl;
    __nv_bfloat16 *wqh, *wql, *woh, *wol, *w1h, *w1l, *w2h, *w2l;
    cudaGetSymbolAddress((void**)&qkv, g_qkv);
    cudaGetSymbolAddress((void**)&ctx, g_ctx);
    cudaGetSymbolAddress((void**)&tmp, g_tmp);
    cudaGetSymbolAddress((void**)&x1,  g_x1);
    cudaGetSymbolAddress((void**)&ah,  g_act_h);
    cudaGetSymbolAddress((void**)&al,  g_act_l);
    cudaGetSymbolAddress((void**)&fh,  g_ffh_h);
    cudaGetSymbolAddress((void**)&fl,  g_ffh_l);
    cudaGetSymbolAddress((void**)&wqh, g_wqkv_h);
    cudaGetSymbolAddress((void**)&wql, g_wqkv_l);
    cudaGetSymbolAddress((void**)&woh, g_wout_h);
    cudaGetSymbolAddress((void**)&wol, g_wout_l);
    cudaGetSymbolAddress((void**)&w1h, g_wff1_h);
    cudaGetSymbolAddress((void**)&w1l, g_wff1_l);
    cudaGetSymbolAddress((void**)&w2h, g_wff2_h);
    cudaGetSymbolAddress((void**)&w2l, g_wff2_l);

    cudaFuncSetAttribute(gemm_mma<0>, cudaFuncAttributeMaxDynamicSharedMemorySize, GEMM_SMEM);
    cudaFuncSetAttribute(gemm_mma<1>, cudaFuncAttributeMaxDynamicSharedMemorySize, GEMM_SMEM);
    cudaFuncSetAttribute(gemm_mma<2>, cudaFuncAttributeMaxDynamicSharedMemorySize, GEMM_SMEM);

    dim3 tb(32, 8);
    // 0) transpose+split weights -> [N,K] bf16 hi/lo
    transpose_split_kernel<<<dim3(D3   / 32, DMODEL / 32), tb>>>(W_qkv, wqh, wql, DMODEL, D3);
    transpose_split_kernel<<<dim3(DMODEL / 32, DMODEL / 32), tb>>>(W_out, woh, wol, DMODEL, DMODEL);
    transpose_split_kernel<<<dim3(DFF  / 32, DMODEL / 32), tb>>>(W_ff1, w1h, w1l, DMODEL, DFF);
    transpose_split_kernel<<<dim3(DMODEL / 32, DFF / 32), tb>>>(W_ff2, w2h, w2l, DFF, DMODEL);

    // 1) split X; QKV projection
    convert_split_kernel<<<(M_ROWS * DMODEL / 4) / 256, 256>>>(X, ah, al, M_ROWS * DMODEL / 4);
    gemm_mma<0><<<dim3(D3 / BN, M_ROWS / BM), 256, GEMM_SMEM>>>(
        ah, al, wqh, wql, b_qkv, nullptr, qkv, nullptr, nullptr, D3, DMODEL);

    // 2) attention
    attn_kernel<<<dim3(SEQ / QTILE, 8 * NHEAD), 64>>>(qkv, ctx);

    // 3) split ctx; out-proj + residual(X)
    convert_split_kernel<<<(M_ROWS * DMODEL / 4) / 256, 256>>>(ctx, ah, al, M_ROWS * DMODEL / 4);
    gemm_mma<1><<<dim3(DMODEL / BN, M_ROWS / BM), 256, GEMM_SMEM>>>(
        ah, al, woh, wol, b_out, X, tmp, nullptr, nullptr, DMODEL, DMODEL);

    // 4) LN1 -> x1 fp32 + split
    ln_kernel<1><<<M_ROWS, 256>>>(tmp, ln1_g, ln1_b, x1, ah, al);

    // 5) FF1 + GELU -> split bf16 directly
    gemm_mma<2><<<dim3(DFF / BN, M_ROWS / BM), 256, GEMM_SMEM>>>(
        ah, al, w1h, w1l, b_ff1, nullptr, nullptr, fh, fl, DFF, DMODEL);

    // 6) FF2 + residual(x1)
    gemm_mma<1><<<dim3(DMODEL / BN, M_ROWS / BM), 256, GEMM_SMEM>>>(
        fh, fl, w2h, w2l, b_ff2, x1, tmp, nullptr, nullptr, DMODEL, DFF);

    // 7) LN2 -> out
    ln_kernel<0><<<M_ROWS, 256>>>(tmp, ln2_g, ln2_b, out, nullptr, nullptr);
}

// round 10
// speedup vs baseline: 2.2805x; 1.2990x over previous
#include <cuda_runtime.h>
#include <cuda_bf16.h>
#include <math.h>
#include <stdint.h>

// ----------------------------------------------------------------------------
// Problem constants: B=8, T=1024, D=1024, H=16, HD=64.  M = B*T = 8192.
// ----------------------------------------------------------------------------
#define M_ROWS 8192
#define DMODEL 1024
#define D3     3072
#define DFF    4096
#define NHEAD  16
#define HDIM   64
#define SEQ    1024

// ----------------------------------------------------------------------------
// Scratch (device globals -- no cudaMalloc allowed)
// ----------------------------------------------------------------------------
__device__ __nv_bfloat16 g_qkv_h[M_ROWS * D3];       // QKV split hi
__device__ __nv_bfloat16 g_qkv_l[M_ROWS * D3];       // QKV split lo
__device__ float g_tmp[M_ROWS * DMODEL];             // fp32 pre-LN buffers
__device__ float g_x1 [M_ROWS * DMODEL];
__device__ __nv_bfloat16 g_act_h[M_ROWS * DMODEL];   // activation hi (X / ctx / x1)
__device__ __nv_bfloat16 g_act_l[M_ROWS * DMODEL];   // activation lo
__device__ __nv_bfloat16 g_ffh_h[M_ROWS * DFF];      // FF1 out hi
__device__ __nv_bfloat16 g_ffh_l[M_ROWS * DFF];      // FF1 out lo
// weights, transposed to [N,K], split hi/lo
__device__ __nv_bfloat16 g_wqkv_h[DMODEL * D3];
__device__ __nv_bfloat16 g_wqkv_l[DMODEL * D3];
__device__ __nv_bfloat16 g_wout_h[DMODEL * DMODEL];
__device__ __nv_bfloat16 g_wout_l[DMODEL * DMODEL];
__device__ __nv_bfloat16 g_wff1_h[DMODEL * DFF];
__device__ __nv_bfloat16 g_wff1_l[DMODEL * DFF];
__device__ __nv_bfloat16 g_wff2_h[DFF * DMODEL];
__device__ __nv_bfloat16 g_wff2_l[DFF * DMODEL];

// ----------------------------------------------------------------------------
// PTX helpers (compute_103-baseline legal: cp.async / ldmatrix / mma.sync)
// ----------------------------------------------------------------------------
__device__ __forceinline__ uint32_t smem_to_u32(const void* smem_ptr) {
    uint32_t addr;
    asm("{ .reg .u64 tmp; cvta.to.shared.u64 tmp, %1; cvt.u32.u64 %0, tmp; }"
        : "=r"(addr) : "l"(smem_ptr));
    return addr;
}

__device__ __forceinline__ void cp16(uint32_t smem_addr, const void* gptr) {
    asm volatile("cp.async.cg.shared.global [%0], [%1], 16;"
                 :: "r"(smem_addr), "l"(gptr));
}
#define CP_COMMIT() asm volatile("cp.async.commit_group;" ::: "memory")
#define CP_WAIT1()  asm volatile("cp.async.wait_group 1;" ::: "memory")

__device__ __forceinline__ void ldsm4(uint32_t* d, uint32_t addr) {
    asm volatile("ldmatrix.sync.aligned.m8n8.x4.shared.b16 {%0,%1,%2,%3}, [%4];"
        : "=r"(d[0]), "=r"(d[1]), "=r"(d[2]), "=r"(d[3]) : "r"(addr));
}
__device__ __forceinline__ void ldsm2(uint32_t* d, uint32_t addr) {
    asm volatile("ldmatrix.sync.aligned.m8n8.x2.shared.b16 {%0,%1}, [%2];"
        : "=r"(d[0]), "=r"(d[1]) : "r"(addr));
}
__device__ __forceinline__ void ldsm2t(uint32_t* d, uint32_t addr) {
    asm volatile("ldmatrix.sync.aligned.m8n8.x2.trans.shared.b16 {%0,%1}, [%2];"
        : "=r"(d[0]), "=r"(d[1]) : "r"(addr));
}

__device__ __forceinline__ void mma16816(float* c, const uint32_t* a, const uint32_t* b) {
    asm volatile("mma.sync.aligned.m16n8k16.row.col.f32.bf16.bf16.f32 "
        "{%0,%1,%2,%3}, {%4,%5,%6,%7}, {%8,%9}, {%0,%1,%2,%3};"
        : "+f"(c[0]), "+f"(c[1]), "+f"(c[2]), "+f"(c[3])
        : "r"(a[0]), "r"(a[1]), "r"(a[2]), "r"(a[3]), "r"(b[0]), "r"(b[1]));
}

// ----------------------------------------------------------------------------
// Split: fp32 -> (bf16 hi, bf16 lo) so x ~= hi + lo
// ----------------------------------------------------------------------------
__device__ __forceinline__ void split2(float a, float b, uint32_t& h, uint32_t& l) {
    __nv_bfloat16 ha = __float2bfloat16(a);
    __nv_bfloat16 hb = __float2bfloat16(b);
    __nv_bfloat16 la = __float2bfloat16(a - __bfloat162float(ha));
    __nv_bfloat16 lb = __float2bfloat16(b - __bfloat162float(hb));
    __nv_bfloat162 hp(ha, hb), lp(la, lb);
    h = *(uint32_t*)&hp; l = *(uint32_t*)&lp;
}

__global__ __launch_bounds__(256) void convert_split_kernel(
    const float* __restrict__ x, __nv_bfloat16* __restrict__ h,
    __nv_bfloat16* __restrict__ l, int n4)
{
    int i = blockIdx.x * 256 + threadIdx.x;
    if (i >= n4) return;
    float4 v = ((const float4*)x)[i];
    uint32_t h0, l0, h1, l1;
    split2(v.x, v.y, h0, l0);
    split2(v.z, v.w, h1, l1);
    ((uint2*)h)[i] = make_uint2(h0, h1);
    ((uint2*)l)[i] = make_uint2(l0, l1);
}

// W [K,N] fp32 row-major -> Wt hi/lo [N,K] bf16 (32x32 tiles)
__global__ __launch_bounds__(256) void transpose_split_kernel(
    const float* __restrict__ W, __nv_bfloat16* __restrict__ h,
    __nv_bfloat16* __restrict__ l, int K, int N)
{
    __shared__ float t[32][33];
    const int tx = threadIdx.x;
    const int ty = threadIdx.y;
    const int k0 = blockIdx.y * 32;
    const int n0 = blockIdx.x * 32;
    #pragma unroll
    for (int r = 0; r < 4; r++)
        t[ty * 4 + r][tx] = W[(size_t)(k0 + ty * 4 + r) * N + n0 + tx];
    __syncthreads();
    #pragma unroll
    for (int r = 0; r < 4; r++) {
        int n = n0 + ty * 4 + r;
        float v = t[tx][ty * 4 + r];
        __nv_bfloat16 hv = __float2bfloat16(v);
        __nv_bfloat16 lv = __float2bfloat16(v - __bfloat162float(hv));
        h[(size_t)n * K + k0 + tx] = hv;
        l[(size_t)n * K + k0 + tx] = lv;
    }
}

// ----------------------------------------------------------------------------
// mma.sync split-bf16 GEMM:  C[M,N] = A[M,K] @ Bt[N,K]^T + bias (+ epilogue)
//   A ~ Ah + Al (bf16 [M,K]);  B ~ Bh + Bl (bf16 [N,K]).
//   A*B ~= Ah*Bh + Ah*Bl + Al*Bh  (fp32 accumulation).
// Tile: 128x128, BK=32, 256 threads (8 warps, each 64x32), 3-stage cp.async.
// EPI: 0 = bias -> fp32;  1 = bias + residual -> fp32;
//      2 = bias + exact GELU -> split bf16;  3 = bias -> split bf16
// ----------------------------------------------------------------------------
#define BM 128
#define BN 128
#define BK 32
#define ROWB 80
#define AH_OFF 0
#define AL_OFF 10240
#define BH_OFF 20480
#define BL_OFF 30720
#define STAGE_BYTES 40960
#define GEMM_SMEM (3 * STAGE_BYTES)

__device__ __forceinline__ float gelu_exact(float x) {
    return 0.5f * x * (1.0f + erff(x * 0.70710678118654752440f));
}

template <int EPI>
__global__ __launch_bounds__(256) void gemm_mma(
    const __nv_bfloat16* __restrict__ Ah, const __nv_bfloat16* __restrict__ Al,
    const __nv_bfloat16* __restrict__ Bh, const __nv_bfloat16* __restrict__ Bl,
    const float* __restrict__ bias, const float* __restrict__ res,
    float* __restrict__ C, __nv_bfloat16* __restrict__ Ch,
    __nv_bfloat16* __restrict__ Cl, int N, int K)
{
    extern __shared__ char smem[];
    const uint32_t sbase = smem_to_u32(smem);
    const int tid  = threadIdx.x;
    const int wid  = tid >> 5;
    const int lane = tid & 31;
    const int m0 = blockIdx.y * BM;
    const int n0 = blockIdx.x * BN;

    const int r  = tid >> 1;
    const int c2 = (tid & 1) * 2;

    const int wm = (wid & 1) * 64;
    const int wn = (wid >> 1) * 32;

    float acc[4][4][4];
    #pragma unroll
    for (int i = 0; i < 4; i++)
        #pragma unroll
        for (int j = 0; j < 4; j++)
            #pragma unroll
            for (int k = 0; k < 4; k++) acc[i][j][k] = 0.0f;

    const int KT = K / BK;

    auto load_stage = [&](int it, int s) {
        const int kc = it * BK;
        const uint32_t st = sbase + s * STAGE_BYTES;
        const uint32_t sa = st + r * ROWB + c2 * 16;
        const size_t ga = (size_t)(m0 + r) * K + kc + c2 * 8;
        const size_t gb = (size_t)(n0 + r) * K + kc + c2 * 8;
        cp16(sa + AH_OFF,      Ah + ga);
        cp16(sa + AH_OFF + 16, Ah + ga + 8);
        cp16(sa + AL_OFF,      Al + ga);
        cp16(sa + AL_OFF + 16, Al + ga + 8);
        cp16(sa + BH_OFF,      Bh + gb);
        cp16(sa + BH_OFF + 16, Bh + gb + 8);
        cp16(sa + BL_OFF,      Bl + gb);
        cp16(sa + BL_OFF + 16, Bl + gb + 8);
    };

    load_stage(0, 0); CP_COMMIT();
    load_stage(1, 1); CP_COMMIT();

    for (int it = 0; it < KT; it++) {
        CP_WAIT1();
        __syncthreads();
        const int nx = it + 2;
        if (nx < KT) load_stage(nx, nx % 3);
        CP_COMMIT();

        const uint32_t st = sbase + (it % 3) * STAGE_BYTES;
        #pragma unroll
        for (int ks = 0; ks < 2; ks++) {
            const int kb  = (ks * 16 + (lane >> 4) * 8) * 2;
            const int kbB = (ks * 16 + ((lane >> 3) & 1) * 8) * 2;
            uint32_t a_h[4][4], a_l[4][4], b_h[4][2], b_l[4][2];
            #pragma unroll
            for (int mf = 0; mf < 4; mf++) {
                uint32_t ra = st + (wm + mf * 16 + (lane & 15)) * ROWB + kb;
                ldsm4(a_h[mf], ra + AH_OFF);
                ldsm4(a_l[mf], ra + AL_OFF);
            }
            #pragma unroll
            for (int nf = 0; nf < 4; nf++) {
                uint32_t rb = st + (wn + nf * 8 + (lane & 7)) * ROWB + kbB;
                ldsm2(b_h[nf], rb + BH_OFF);
                ldsm2(b_l[nf], rb + BL_OFF);
            }
            #pragma unroll
            for (int mf = 0; mf < 4; mf++)
                #pragma unroll
                for (int nf = 0; nf < 4; nf++) {
                    mma16816(acc[mf][nf], a_h[mf], b_h[nf]);
                    mma16816(acc[mf][nf], a_h[mf], b_l[nf]);
                    mma16816(acc[mf][nf], a_l[mf], b_h[nf]);
                }
        }
    }

    #pragma unroll
    for (int mf = 0; mf < 4; mf++) {
        const int m = m0 + wm + mf * 16 + (lane >> 2);
        #pragma unroll
        for (int nf = 0; nf < 4; nf++) {
            const int n = n0 + wn + nf * 8 + (lane & 3) * 2;
            float2 bv = *(const float2*)(bias + n);
            float* a = acc[mf][nf];
            float v0 = a[0] + bv.x, v1 = a[1] + bv.y;
            float v2 = a[2] + bv.x, v3 = a[3] + bv.y;
            if (EPI == 1) {
                float2 r0 = *(const float2*)(res + (size_t)m * N + n);
                float2 r1 = *(const float2*)(res + (size_t)(m + 8) * N + n);
                v0 += r0.x; v1 += r0.y; v2 += r1.x; v3 += r1.y;
            }
            if (EPI == 2) {
                v0 = gelu_exact(v0); v1 = gelu_exact(v1);
                v2 = gelu_exact(v2); v3 = gelu_exact(v3);
            }
            if (EPI >= 2) {
                uint32_t h0, l0, h1, l1;
                split2(v0, v1, h0, l0);
                split2(v2, v3, h1, l1);
                *(uint32_t*)(Ch + (size_t)m * N + n)       = h0;
                *(uint32_t*)(Cl + (size_t)m * N + n)       = l0;
                *(uint32_t*)(Ch + (size_t)(m + 8) * N + n) = h1;
                *(uint32_t*)(Cl + (size_t)(m + 8) * N + n) = l1;
            } else {
                *(float2*)(C + (size_t)m * N + n)       = make_float2(v0, v1);
                *(float2*)(C + (size_t)(m + 8) * N + n) = make_float2(v2, v3);
            }
        }
    }
}

// ----------------------------------------------------------------------------
// Tensor-core flash attention (split bf16).
// CTA: 64 q rows x one (b,h); 4 warps x 16 q rows; K tiles of 64 keys.
// S = Qh*Kh + Qh*Kl + Ql*Kh ; softmax in mma layout ; P split hi/lo ;
// O += Ph*Vh + Ph*Vl + Pl*Vh  (V fragments via ldmatrix.trans).
// Emits ctx directly as split bf16 (oh, ol).
// ----------------------------------------------------------------------------
#define AROW 144                       // smem row stride bytes (64 halves + pad)
#define AQ_BYTES (64 * AROW)           // 9216 per 64x64 tile
#define AST (4 * AQ_BYTES)             // stage: Kh,Kl,Vh,Vl = 36864
#define ATT_SMEM (2 * AQ_BYTES + 2 * AST)  // 92160

__global__ __launch_bounds__(128) void attn_mma(
    const __nv_bfloat16* __restrict__ qh, const __nv_bfloat16* __restrict__ ql,
    __nv_bfloat16* __restrict__ oh, __nv_bfloat16* __restrict__ ol)
{
    extern __shared__ char smem[];
    const uint32_t sb = smem_to_u32(smem);
    const int tid  = threadIdx.x;
    const int w    = tid >> 5;
    const int lane = tid & 31;
    const int bh = blockIdx.y;
    const int b  = bh >> 4;
    const int h  = bh & 15;
    const int q0 = blockIdx.x * 64;

    const uint32_t QHs = sb;
    const uint32_t QLs = sb + AQ_BYTES;

    const int r  = tid >> 1;           // 0..63
    const int cb = (tid & 1) * 4;      // chunk base (16B chunks)

    // Q tile loads (with group 0)
    {
        const size_t g = (size_t)(b * SEQ + q0 + r) * D3 + h * HDIM + cb * 8;
        const uint32_t o = r * AROW + cb * 16;
        #pragma unroll
        for (int c = 0; c < 4; c++) {
            cp16(QHs + o + c * 16, qh + g + c * 8);
            cp16(QLs + o + c * 16, ql + g + c * 8);
        }
    }
    auto load_kv = [&](int kt, int s) {
        const uint32_t st = sb + 2 * AQ_BYTES + s * AST;
        const size_t gk = (size_t)(b * SEQ + kt * 64 + r) * D3 + DMODEL + h * HDIM + cb * 8;
        const size_t gv = gk + DMODEL;
        const uint32_t o = r * AROW + cb * 16;
        #pragma unroll
        for (int c = 0; c < 4; c++) {
            cp16(st + o + c * 16,                 qh + gk + c * 8);
            cp16(st + AQ_BYTES + o + c * 16,      ql + gk + c * 8);
            cp16(st + 2 * AQ_BYTES + o + c * 16,  qh + gv + c * 8);
            cp16(st + 3 * AQ_BYTES + o + c * 16,  ql + gv + c * 8);
        }
    };
    load_kv(0, 0); CP_COMMIT();
    load_kv(1, 1); CP_COMMIT();

    uint32_t qfh[4][4], qfl[4][4];
    float O[8][4];
    #pragma unroll
    for (int i = 0; i < 8; i++)
        #pragma unroll
        for (int j = 0; j < 4; j++) O[i][j] = 0.0f;
    float m0 = -1e30f, m1 = -1e30f, l0 = 0.0f, l1 = 0.0f;

    for (int kt = 0; kt < SEQ / 64; kt++) {
        CP_WAIT1();
        __syncthreads();
        if (kt == 0) {
            #pragma unroll
            for (int kf = 0; kf < 4; kf++) {
                uint32_t qa = QHs + (w * 16 + (lane & 15)) * AROW + kf * 32 + (lane >> 4) * 16;
                ldsm4(qfh[kf], qa);
                ldsm4(qfl[kf], qa + AQ_BYTES);
            }
        }
        const uint32_t st = sb + 2 * AQ_BYTES + (kt & 1) * AST;

        // ---- S = Q K^T  (warp: 16q x 64k) ----
        float s[8][4];
        #pragma unroll
        for (int i = 0; i < 8; i++)
            #pragma unroll
            for (int j = 0; j < 4; j++) s[i][j] = 0.0f;
        #pragma unroll
        for (int kf = 0; kf < 4; kf++) {
            #pragma unroll
            for (int nf = 0; nf < 8; nf++) {
                uint32_t ka = st + (nf * 8 + (lane & 7)) * AROW + kf * 32 + ((lane >> 3) & 1) * 16;
                uint32_t b_h[2], b_l[2];
                ldsm2(b_h, ka);
                ldsm2(b_l, ka + AQ_BYTES);
                mma16816(s[nf], qfh[kf], b_h);
                mma16816(s[nf], qfh[kf], b_l);
                mma16816(s[nf], qfl[kf], b_h);
            }
        }

        // ---- online softmax in mma layout ----
        float mx0 = -1e30f, mx1 = -1e30f;
        #pragma unroll
        for (int nf = 0; nf < 8; nf++) {
            s[nf][0] *= 0.125f; s[nf][1] *= 0.125f;
            s[nf][2] *= 0.125f; s[nf][3] *= 0.125f;
            mx0 = fmaxf(mx0, fmaxf(s[nf][0], s[nf][1]));
            mx1 = fmaxf(mx1, fmaxf(s[nf][2], s[nf][3]));
        }
        mx0 = fmaxf(mx0, __shfl_xor_sync(0xffffffffu, mx0, 1));
        mx0 = fmaxf(mx0, __shfl_xor_sync(0xffffffffu, mx0, 2));
        mx1 = fmaxf(mx1, __shfl_xor_sync(0xffffffffu, mx1, 1));
        mx1 = fmaxf(mx1, __shfl_xor_sync(0xffffffffu, mx1, 2));
        float mn0 = fmaxf(m0, mx0), mn1 = fmaxf(m1, mx1);
        float cr0 = __expf(m0 - mn0), cr1 = __expf(m1 - mn1);
        float sm0 = 0.0f, sm1 = 0.0f;
        #pragma unroll
        for (int nf = 0; nf < 8; nf++) {
            s[nf][0] = __expf(s[nf][0] - mn0); sm0 += s[nf][0];
            s[nf][1] = __expf(s[nf][1] - mn0); sm0 += s[nf][1];
            s[nf][2] = __expf(s[nf][2] - mn1); sm1 += s[nf][2];
            s[nf][3] = __expf(s[nf][3] - mn1); sm1 += s[nf][3];
        }
        sm0 += __shfl_xor_sync(0xffffffffu, sm0, 1);
        sm0 += __shfl_xor_sync(0xffffffffu, sm0, 2);
        sm1 += __shfl_xor_sync(0xffffffffu, sm1, 1);
        sm1 += __shfl_xor_sync(0xffffffffu, sm1, 2);
        l0 = l0 * cr0 + sm0; m0 = mn0;
        l1 = l1 * cr1 + sm1; m1 = mn1;
        #pragma unroll
        for (int nf = 0; nf < 8; nf++) {
            O[nf][0] *= cr0; O[nf][1] *= cr0;
            O[nf][2] *= cr1; O[nf][3] *= cr1;
        }

        // ---- O += P V  (P repacked acc->A frags, V via ldmatrix.trans) ----
        #pragma unroll
        for (int kf = 0; kf < 4; kf++) {
            uint32_t pa[4], pl[4];
            split2(s[2*kf][0],   s[2*kf][1],   pa[0], pl[0]);
            split2(s[2*kf][2],   s[2*kf][3],   pa[1], pl[1]);
            split2(s[2*kf+1][0], s[2*kf+1][1], pa[2], pl[2]);
            split2(s[2*kf+1][2], s[2*kf+1][3], pa[3], pl[3]);
            #pragma unroll
            for (int nf = 0; nf < 8; nf++) {
                uint32_t va = st + 2 * AQ_BYTES + (kf * 16 + (lane & 15)) * AROW + nf * 16;
                uint32_t b_h[2], b_l[2];
                ldsm2t(b_h, va);
                ldsm2t(b_l, va + AQ_BYTES);
                mma16816(O[nf], pa, b_h);
                mma16816(O[nf], pa, b_l);
                mma16816(O[nf], pl, b_h);
            }
        }

        __syncthreads();
        if (kt + 2 < SEQ / 64) load_kv(kt + 2, kt & 1);
        CP_COMMIT();
    }

    // ---- write ctx as split bf16 ----
    {
        float i0 = 1.0f / l0, i1 = 1.0f / l1;
        const int mr = q0 + w * 16 + (lane >> 2);
        const size_t row0 = (size_t)(b * SEQ + mr) * DMODEL;
        const size_t row1 = row0 + 8 * DMODEL;
        #pragma unroll
        for (int nf = 0; nf < 8; nf++) {
            const int n = h * HDIM + nf * 8 + (lane & 3) * 2;
            uint32_t hi, lo;
            split2(O[nf][0] * i0, O[nf][1] * i0, hi, lo);
            *(uint32_t*)(oh + row0 + n) = hi;
            *(uint32_t*)(ol + row0 + n) = lo;
            split2(O[nf][2] * i1, O[nf][3] * i1, hi, lo);
            *(uint32_t*)(oh + row1 + n) = hi;
            *(uint32_t*)(ol + row1 + n) = lo;
        }
    }
}

// ----------------------------------------------------------------------------
// LayerNorm; SPLIT=1 additionally emits bf16 hi/lo of the output
// ----------------------------------------------------------------------------
template <int SPLIT>
__global__ __launch_bounds__(256) void ln_kernel(
    const float* __restrict__ x, const float* __restrict__ g,
    const float* __restrict__ beta, float* __restrict__ y,
    __nv_bfloat16* __restrict__ yh, __nv_bfloat16* __restrict__ yl)
{
    const int row = blockIdx.x;
    const int tid = threadIdx.x;
    const float* xr = x + (size_t)row * DMODEL;

    float4 v = *(const float4*)(xr + tid * 4);
    float s  = v.x + v.y + v.z + v.w;
    float sq = v.x*v.x + v.y*v.y + v.z*v.z + v.w*v.w;

    #pragma unroll
    for (int off = 16; off > 0; off >>= 1) {
        s  += __shfl_xor_sync(0xffffffffu, s,  off);
        sq += __shfl_xor_sync(0xffffffffu, sq, off);
    }
    __shared__ float ss[8], ssq[8];
    if ((tid & 31) == 0) { ss[tid >> 5] = s; ssq[tid >> 5] = sq; }
    __syncthreads();
    float tot = 0.0f, totq = 0.0f;
    #pragma unroll
    for (int i = 0; i < 8; i++) { tot += ss[i]; totq += ssq[i]; }

    const float mu   = tot * (1.0f / DMODEL);
    const float var  = totq * (1.0f / DMODEL) - mu * mu;
    const float rstd = rsqrtf(var + 1e-5f);

    float4 gg = *(const float4*)(g + tid * 4);
    float4 bb = *(const float4*)(beta + tid * 4);
    float4 o;
    o.x = (v.x - mu) * rstd * gg.x + bb.x;
    o.y = (v.y - mu) * rstd * gg.y + bb.y;
    o.z = (v.z - mu) * rstd * gg.z + bb.z;
    o.w = (v.w - mu) * rstd * gg.w + bb.w;
    *(float4*)(y + (size_t)row * DMODEL + tid * 4) = o;

    if (SPLIT) {
        uint32_t h0, l0, h1, l1;
        split2(o.x, o.y, h0, l0);
        split2(o.z, o.w, h1, l1);
        ((uint2*)(yh + (size_t)row * DMODEL))[tid] = make_uint2(h0, h1);
        ((uint2*)(yl + (size_t)row * DMODEL))[tid] = make_uint2(l0, l1);
    }
}

// ----------------------------------------------------------------------------
// kernel_launch
// Inputs: 0 X, 1 W_qkv, 2 b_qkv, 3 W_out, 4 b_out, 5 ln1_g, 6 ln1_b,
//         7 ln2_g, 8 ln2_b, 9 W_ff1, 10 b_ff1, 11 W_ff2, 12 b_ff2
// ----------------------------------------------------------------------------
extern "C" void kernel_launch(void* const* d_in, const int* in_sizes, int n_in,
                              void* d_out, int out_size)
{
    const float* X      = (const float*)d_in[0];
    const float* W_qkv  = (const float*)d_in[1];
    const float* b_qkv  = (const float*)d_in[2];
    const float* W_out  = (const float*)d_in[3];
    const float* b_out  = (const float*)d_in[4];
    const float* ln1_g  = (const float*)d_in[5];
    const float* ln1_b  = (const float*)d_in[6];
    const float* ln2_g  = (const float*)d_in[7];
    const float* ln2_b  = (const float*)d_in[8];
    const float* W_ff1  = (const float*)d_in[9];
    const float* b_ff1  = (const float*)d_in[10];
    const float* W_ff2  = (const float*)d_in[11];
    const float* b_ff2  = (const float*)d_in[12];
    float* out = (float*)d_out;

    float *tmp, *x1;
    __nv_bfloat16 *qkh, *qkl, *ah, *al, *fh, *fl;
    __nv_bfloat16 *wqh, *wql, *woh, *wol, *w1h, *w1l, *w2h, *w2l;
    cudaGetSymbolAddress((void**)&qkh, g_qkv_h);
    cudaGetSymbolAddress((void**)&qkl, g_qkv_l);
    cudaGetSymbolAddress((void**)&tmp, g_tmp);
    cudaGetSymbolAddress((void**)&x1,  g_x1);
    cudaGetSymbolAddress((void**)&ah,  g_act_h);
    cudaGetSymbolAddress((void**)&al,  g_act_l);
    cudaGetSymbolAddress((void**)&fh,  g_ffh_h);
    cudaGetSymbolAddress((void**)&fl,  g_ffh_l);
    cudaGetSymbolAddress((void**)&wqh, g_wqkv_h);
    cudaGetSymbolAddress((void**)&wql, g_wqkv_l);
    cudaGetSymbolAddress((void**)&woh, g_wout_h);
    cudaGetSymbolAddress((void**)&wol, g_wout_l);
    cudaGetSymbolAddress((void**)&w1h, g_wff1_h);
    cudaGetSymbolAddress((void**)&w1l, g_wff1_l);
    cudaGetSymbolAddress((void**)&w2h, g_wff2_h);
    cudaGetSymbolAddress((void**)&w2l, g_wff2_l);

    cudaFuncSetAttribute(gemm_mma<0>, cudaFuncAttributeMaxDynamicSharedMemorySize, GEMM_SMEM);
    cudaFuncSetAttribute(gemm_mma<1>, cudaFuncAttributeMaxDynamicSharedMemorySize, GEMM_SMEM);
    cudaFuncSetAttribute(gemm_mma<2>, cudaFuncAttributeMaxDynamicSharedMemorySize, GEMM_SMEM);
    cudaFuncSetAttribute(gemm_mma<3>, cudaFuncAttributeMaxDynamicSharedMemorySize, GEMM_SMEM);
    cudaFuncSetAttribute(attn_mma, cudaFuncAttributeMaxDynamicSharedMemorySize, ATT_SMEM);

    dim3 tb(32, 8);
    // 0) transpose+split weights -> [N,K] bf16 hi/lo
    transpose_split_kernel<<<dim3(D3   / 32, DMODEL / 32), tb>>>(W_qkv, wqh, wql, DMODEL, D3);
    transpose_split_kernel<<<dim3(DMODEL / 32, DMODEL / 32), tb>>>(W_out, woh, wol, DMODEL, DMODEL);
    transpose_split_kernel<<<dim3(DFF  / 32, DMODEL / 32), tb>>>(W_ff1, w1h, w1l, DMODEL, DFF);
    transpose_split_kernel<<<dim3(DMODEL / 32, DFF / 32), tb>>>(W_ff2, w2h, w2l, DFF, DMODEL);

    // 1) split X; QKV projection -> split bf16 qkv
    convert_split_kernel<<<(M_ROWS * DMODEL / 4) / 256, 256>>>(X, ah, al, M_ROWS * DMODEL / 4);
    gemm_mma<3><<<dim3(D3 / BN, M_ROWS / BM), 256, GEMM_SMEM>>>(
        ah, al, wqh, wql, b_qkv, nullptr, nullptr, qkh, qkl, D3, DMODEL);

    // 2) tensor-core attention -> ctx split bf16 (reuses act buffers)
    attn_mma<<<dim3(SEQ / 64, 8 * NHEAD), 128, ATT_SMEM>>>(qkh, qkl, ah, al);

    // 3) out-proj + residual(X) -> tmp fp32
    gemm_mma<1><<<dim3(DMODEL / BN, M_ROWS / BM), 256, GEMM_SMEM>>>(
        ah, al, woh, wol, b_out, X, tmp, nullptr, nullptr, DMODEL, DMODEL);

    // 4) LN1 -> x1 fp32 + split (act buffers)
    ln_kernel<1><<<M_ROWS, 256>>>(tmp, ln1_g, ln1_b, x1, ah, al);

    // 5) FF1 + GELU -> split bf16
    gemm_mma<2><<<dim3(DFF / BN, M_ROWS / BM), 256, GEMM_SMEM>>>(
        ah, al, w1h, w1l, b_ff1, nullptr, nullptr, fh, fl, DFF, DMODEL);

    // 6) FF2 + residual(x1) -> tmp fp32
    gemm_mma<1><<<dim3(DMODEL / BN, M_ROWS / BM), 256, GEMM_SMEM>>>(
        fh, fl, w2h, w2l, b_ff2, x1, tmp, nullptr, nullptr, DMODEL, DFF);

    // 7) LN2 -> out
    ln_kernel<0><<<M_ROWS, 256>>>(tmp, ln2_g, ln2_b, out, nullptr, nullptr);
}